// round 16
// baseline (speedup 1.0000x reference)
#include <cuda_runtime.h>
#include <math.h>

#define NB   512
#define NPG  256
#define EPG  4096
#define FIN  128
#define TCLS 18
#define KTOP 16
#define FSTR 256      // g_feat row: layers 0..3
#define VSH  260      // ht row stride: mult of 4 -> every row 16B-aligned
#define VSL  68       // lt row stride: mult of 4 -> every row 16B-aligned
#define NT   1024
#define RB   (VSL * 4)   // lt row stride in BYTES (272)

__device__ float g_feat[(size_t)NB * NPG * FSTR];

typedef unsigned long long ull;

static __device__ __forceinline__ ull pk2(float lo, float hi) {
    ull r; asm("mov.b64 %0, {%1, %2};" : "=l"(r) : "f"(lo), "f"(hi)); return r;
}
static __device__ __forceinline__ void upk2(ull v, float &lo, float &hi) {
    asm("mov.b64 {%0, %1}, %2;" : "=f"(lo), "=f"(hi) : "l"(v));
}
static __device__ __forceinline__ void fma2(ull &acc, ull a, ull b) {
    asm("fma.rn.f32x2 %0, %1, %2, %0;" : "+l"(acc) : "l"(a), "l"(b));
}
static __device__ __forceinline__ ull add2(ull a, ull b) {
    ull r; asm("add.rn.f32x2 %0, %1, %2;" : "=l"(r) : "l"(a), "l"(b)); return r;
}

// dynamic smem layout (words):
//   ht: 64*VSH = 16640 | lt: 257*VSL = 17476 (row 256 = zero pad; x-chunk1 home during L0)
//   wbufn: 4096 ull = 8192 words (both L0 weight chunks; single chunk for L1-3)
//   invd: 256 | roff: 260 i | cnt: 256 i | eoff: 6144 u32 = 6144 words
#define W_HT   (64 * VSH)
#define W_LT   (257 * VSL)
#define W_WB   8192
#define W_WBUF_BASE (W_HT + W_LT)
#define W_EOFF_BASE (W_WBUF_BASE + W_WB + 256 + 260 + 256)
static_assert(VSH % 4 == 0,         "every ht row 16B-aligned");
static_assert(VSL % 4 == 0,         "every lt row 16B-aligned");
static_assert(W_HT % 4 == 0,        "lt base 16B");
static_assert(W_WBUF_BASE % 4 == 0, "wbufn base 16B (ulonglong2 loads)");
static_assert(W_EOFF_BASE % 4 == 0, "eoff base 16B (uint4 loads)");
static_assert(64 * VSH <= 256 * VSL, "x chunk1 must fit below lt zero-pad row");
#define SMEM_WORDS (W_EOFF_BASE + 6144)
#define SMEM_BYTES (SMEM_WORDS * 4)

__global__ void __launch_bounds__(NT, 1) dgcnn_kernel(
    const float* __restrict__ x, const int* __restrict__ ei,
    const float* __restrict__ w0, const float* __restrict__ b0,
    const float* __restrict__ w1, const float* __restrict__ b1,
    const float* __restrict__ w2, const float* __restrict__ b2,
    const float* __restrict__ w3, const float* __restrict__ b3,
    const float* __restrict__ w4, const float* __restrict__ b4,
    const float* __restrict__ c1w, const float* __restrict__ c1b,
    const float* __restrict__ c2w, const float* __restrict__ c2b,
    const float* __restrict__ d1w, const float* __restrict__ d1b,
    const float* __restrict__ d2w, const float* __restrict__ d2b,
    float* __restrict__ out)
{
    extern __shared__ float sm[];
    float* ht    = sm;                          // [64][VSH] channel-major features
    float* lt    = sm + W_HT;                   // [257][VSL] node-major lin
    ull*   wbufn = (ull*)(sm + W_WBUF_BASE);    // natural channel-pair weights
    float* invd  = sm + W_WBUF_BASE + W_WB;
    int*   roff  = (int*)(invd + 256);
    int*   cnt   = roff + 260;
    unsigned int* eoff = (unsigned int*)(sm + W_EOFF_BASE);   // BYTE offsets, premult by RB
    unsigned char* s8  = (unsigned char*)wbufn;   // union (CSR build phase only)
    unsigned char* d8  = s8 + EPG;

    __shared__ float sc[NPG];
    __shared__ float w4s[64];
    __shared__ int   ord[KTOP];
    __shared__ float c1s[256];
    __shared__ float p1s[128];
    __shared__ float flats[128];
    __shared__ float lasts[32];
    __shared__ float outs[TCLS];
    __shared__ float lse_s;

    const int g = blockIdx.x, tid = threadIdx.x;
    const int eb = g * EPG;

    // ---- edges: graph base 256-aligned, low 8 bits = local id ----
    for (int e = tid; e < EPG; e += NT) {
        s8[e] = (unsigned char)(ei[eb + e] & 255);
        d8[e] = (unsigned char)(ei[(size_t)NB * EPG + eb + e] & 255);
    }
    int* dcn = (int*)ht;  // scratch
    if (tid < NPG) { cnt[tid] = 1; dcn[tid] = 1; }   // dcn starts at 1: self edge in list
    if (tid < VSL) lt[256 * VSL + tid] = 0.0f;       // zero pad row (dummy gather target)
    __syncthreads();
    for (int e = tid; e < EPG; e += NT) {
        atomicAdd(&cnt[s8[e]], 1);
        atomicAdd(&dcn[d8[e]], 1);
    }
    __syncthreads();
    if (tid < NPG) {
        invd[tid] = 1.0f / (float)cnt[tid];
        dcn[tid] = (dcn[tid] + 7) & ~7;          // pad to multiple of 8
    }
    __syncthreads();
    for (int s = 1; s < NPG; s <<= 1) {          // inclusive scan
        int t = 0;
        if (tid < NPG) { t = dcn[tid]; if (tid >= s) t += dcn[tid - s]; }
        __syncthreads();
        if (tid < NPG) dcn[tid] = t;
        __syncthreads();
    }
    if (tid < NPG) roff[tid + 1] = dcn[tid];
    if (tid == 0)  roff[0] = 0;
    __syncthreads();
    if (tid < NPG) {   // self edge occupies first slot; cursor starts after it
        eoff[roff[tid]] = (unsigned int)(tid * RB);
        cnt[tid] = roff[tid] + 1;
    }
    __syncthreads();
    for (int e = tid; e < EPG; e += NT) {
        int p = atomicAdd(&cnt[d8[e]], 1);
        eoff[p] = (unsigned int)((int)s8[e] * RB);   // premultiplied BYTE offset
    }
    __syncthreads();
    if (tid < NPG) {
        int p = cnt[tid], p1 = roff[tid + 1];
        for (; p < p1; p++) eoff[p] = (unsigned int)(256 * RB);  // dummy -> zero row
    }
    __syncthreads();

    const float* Wp[4] = {w0, w1, w2, w3};
    const float* Bp[4] = {b0, b1, b2, b3};
    const int lane  = tid & 31;
    const int cgp   = (tid >> 5) & 7;    // channel group (8 ch)
    const int ngp   = tid >> 8;          // node slice (0..3)
    const int c8    = cgp * 8;
    const int pbase = 2 * (lane + 32 * ngp);   // node pair (pbase, pbase+1)

    // ---- layers 0..3 ----
    for (int L = 0; L < 4; L++) {
        ull accA[4], accB[4];   // accA: node pbase, ch (c8+2j, c8+2j+1); accB: node pbase+1
#pragma unroll
        for (int t = 0; t < 4; t++) { accA[t] = 0ull; accB[t] = 0ull; }

        if (L == 0) {
            // single pass: stage BOTH x chunks (chunk0 -> ht, chunk1 -> lt region)
            float* ht2 = lt;
            for (int i = tid; i < NPG * 32; i += NT) {
                int n = i >> 5, r = i & 31, ch = r >> 4, kq = r & 15;
                float4 v = *(const float4*)(x + (size_t)(g * NPG + n) * FIN + ch * 64 + kq * 4);
                float* hb = ch ? ht2 : ht;
                hb[(kq * 4 + 0) * VSH + n] = v.x;
                hb[(kq * 4 + 1) * VSH + n] = v.y;
                hb[(kq * 4 + 2) * VSH + n] = v.z;
                hb[(kq * 4 + 3) * VSH + n] = v.w;
            }
            // stage BOTH weight chunks as natural channel pairs
            for (int i = tid; i < 4096; i += NT) {
                int j2 = i & 31, k = (i >> 5) & 63, ch = i >> 11;
                float wlo = w0[(2 * j2)     * FIN + ch * 64 + k];
                float whi = w0[(2 * j2 + 1) * FIN + ch * 64 + k];
                wbufn[ch * 2048 + k * 32 + j2] = pk2(wlo, whi);
            }
            __syncthreads();
            const float* hbs[2] = {ht, ht2};
#pragma unroll
            for (int half = 0; half < 2; half++) {   // half 0 fully, then half 1: same FP order
                const float* hb = hbs[half];
                const ull* wb = wbufn + half * 2048 + 4 * cgp;
#pragma unroll 2
                for (int k = 0; k < 64; k++) {
                    ull hp = *(const ull*)(hb + k * VSH + pbase);
                    float h0, h1; upk2(hp, h0, h1);
                    ull d0 = pk2(h0, h0), d1 = pk2(h1, h1);
                    const ulonglong2* wp = (const ulonglong2*)(wb + k * 32);
                    ulonglong2 wa = wp[0], wbv = wp[1];
                    fma2(accA[0], d0, wa.x);  fma2(accA[1], d0, wa.y);
                    fma2(accA[2], d0, wbv.x); fma2(accA[3], d0, wbv.y);
                    fma2(accB[0], d1, wa.x);  fma2(accB[1], d1, wa.y);
                    fma2(accB[2], d1, wbv.x); fma2(accB[3], d1, wbv.y);
                }
            }
            __syncthreads();
        } else {
            const float* WL = Wp[L];
            for (int i = tid; i < 2048; i += NT) {
                int j2 = i & 31, k = i >> 5;
                wbufn[k * 32 + j2] = pk2(WL[(2 * j2) * 64 + k], WL[(2 * j2 + 1) * 64 + k]);
            }
            __syncthreads();
            const ull* wb = wbufn + 4 * cgp;
#pragma unroll 2
            for (int k = 0; k < 64; k++) {
                ull hp = *(const ull*)(ht + k * VSH + pbase);
                float h0, h1; upk2(hp, h0, h1);
                ull d0 = pk2(h0, h0), d1 = pk2(h1, h1);
                const ulonglong2* wp = (const ulonglong2*)(wb + k * 32);
                ulonglong2 wa = wp[0], wbv = wp[1];
                fma2(accA[0], d0, wa.x);  fma2(accA[1], d0, wa.y);
                fma2(accA[2], d0, wbv.x); fma2(accA[3], d0, wbv.y);
                fma2(accB[0], d1, wa.x);  fma2(accB[1], d1, wa.y);
                fma2(accB[2], d1, wbv.x); fma2(accB[3], d1, wbv.y);
            }
            __syncthreads();
        }
        // bias (f32x2) + store lin node-major: 2 STS.128 per node row
        {
            const float* bb = Bp[L];
#pragma unroll
            for (int t = 0; t < 4; t++) {
                ull bp = pk2(bb[c8 + 2 * t], bb[c8 + 2 * t + 1]);
                accA[t] = add2(accA[t], bp);
                accB[t] = add2(accB[t], bp);
            }
            ulonglong2* r0 = (ulonglong2*)(lt + pbase * VSL + c8);
            ulonglong2* r1 = (ulonglong2*)(lt + (pbase + 1) * VSL + c8);
            r0[0] = make_ulonglong2(accA[0], accA[1]);
            r0[1] = make_ulonglong2(accA[2], accA[3]);
            r1[0] = make_ulonglong2(accB[0], accB[1]);
            r1[1] = make_ulonglong2(accB[2], accB[3]);
        }
        __syncthreads();
        // aggregation: lane = channel pair (c2,c2+1); byte-offset edges; self edge in list
        {
            const int c2 = 2 * lane;
            const int grp = tid >> 5;            // 0..31
            const char* lcb = (const char*)(lt + c2);
#pragma unroll
            for (int r = 0; r < 2; r++) {
                const int vb = 4 * grp + 128 * r;
                float tlo[4], thi[4];
#pragma unroll
                for (int j = 0; j < 4; j++) {
                    const int v = vb + j;
                    ull a0 = 0, a1 = 0, a2 = 0, a3 = 0;
                    int e = roff[v], e1 = roff[v + 1];
                    for (; e < e1; e += 8) {
                        uint4 p0 = *(const uint4*)(eoff + e);
                        uint4 p1 = *(const uint4*)(eoff + e + 4);
                        a0 = add2(a0, *(const ull*)(lcb + p0.x));
                        a1 = add2(a1, *(const ull*)(lcb + p0.y));
                        a2 = add2(a2, *(const ull*)(lcb + p0.z));
                        a3 = add2(a3, *(const ull*)(lcb + p0.w));
                        a0 = add2(a0, *(const ull*)(lcb + p1.x));
                        a1 = add2(a1, *(const ull*)(lcb + p1.y));
                        a2 = add2(a2, *(const ull*)(lcb + p1.z));
                        a3 = add2(a3, *(const ull*)(lcb + p1.w));
                    }
                    ull s = add2(add2(a0, a1), add2(a2, a3));
                    float x0, x1; upk2(s, x0, x1);
                    float iv = invd[v];
                    float t0 = tanhf(x0 * iv);
                    float t1 = tanhf(x1 * iv);
                    tlo[j] = t0; thi[j] = t1;
                    *(float2*)(g_feat + (size_t)(g * NPG + v) * FSTR + L * 64 + c2) = make_float2(t0, t1);
                }
                *(float4*)(ht + c2 * VSH + vb)       = make_float4(tlo[0], tlo[1], tlo[2], tlo[3]);
                *(float4*)(ht + (c2 + 1) * VSH + vb) = make_float4(thi[0], thi[1], thi[2], thi[3]);
            }
        }
        __syncthreads();
    }

    // ---- layer 4: sort scores ----
    if (tid < 64) w4s[tid] = w4[tid];
    __syncthreads();
    if (tid < NPG) {
        float s = b4[0];
#pragma unroll 4
        for (int k = 0; k < 64; k++) s += ht[k * VSH + tid] * w4s[k];
        lt[tid * VSL] = s;
    }
    __syncthreads();
    if (tid < NPG) {
        const char* ltb = (const char*)lt;
        float a0 = 0.f, a1 = 0.f, a2 = 0.f, a3 = 0.f;   // self edge is in the list
        int e = roff[tid], e1 = roff[tid + 1];
        for (; e < e1; e += 8) {
            uint4 p0 = *(const uint4*)(eoff + e);
            uint4 p1 = *(const uint4*)(eoff + e + 4);
            a0 += *(const float*)(ltb + p0.x); a1 += *(const float*)(ltb + p0.y);
            a2 += *(const float*)(ltb + p0.z); a3 += *(const float*)(ltb + p0.w);
            a0 += *(const float*)(ltb + p1.x); a1 += *(const float*)(ltb + p1.y);
            a2 += *(const float*)(ltb + p1.z); a3 += *(const float*)(ltb + p1.w);
        }
        float a = (a0 + a1) + (a2 + a3);
        sc[tid] = tanhf(a * invd[tid]);
    }
    __syncthreads();

    // ---- stable top-16: single warp shfl (val desc, idx asc) ----
    if (tid < 32) {
        float v[8];
        const int base = tid * 8;
#pragma unroll
        for (int t = 0; t < 8; t++) v[t] = sc[base + t];
        for (int r = 0; r < KTOP; r++) {
            float bv = v[0]; int bi = base;
#pragma unroll
            for (int t = 1; t < 8; t++)
                if (v[t] > bv) { bv = v[t]; bi = base + t; }
#pragma unroll
            for (int off = 16; off > 0; off >>= 1) {
                float ov = __shfl_xor_sync(0xffffffffu, bv, off);
                int   oi = __shfl_xor_sync(0xffffffffu, bi, off);
                if (ov > bv || (ov == bv && oi < bi)) { bv = ov; bi = oi; }
            }
            if (tid == 0) ord[r] = bi;
            if ((bi >> 3) == tid) v[bi & 7] = -3.4e38f;
        }
    }
    __syncthreads();

    // ---- head (tk in lt, c1ws in ht; both stride 260) ----
    float* tk   = lt;
    float* c1ws = ht;
    for (int i = tid; i < 16 * 257; i += NT) {
        int o = i / 257, d = i - o * 257;
        c1ws[o * 260 + d] = c1w[i];
    }
    for (int i = tid; i < KTOP * 257; i += NT) {
        int l = i / 257, d = i - l * 257;
        tk[l * 260 + d] = (d < 256) ? g_feat[(size_t)(g * NPG + ord[l]) * FSTR + d] : sc[ord[l]];
    }
    __syncthreads();

    if (tid < 256) {
        int o = tid & 15, l = tid >> 4;
        const float4* tr = (const float4*)(tk + l * 260);
        const float4* wr = (const float4*)(c1ws + o * 260);
        float s0 = 0.f, s1 = 0.f, s2 = 0.f, s3 = 0.f;
#pragma unroll 4
        for (int d = 0; d < 64; d++) {
            float4 a = tr[d], b = wr[d];
            s0 += a.x * b.x; s1 += a.y * b.y; s2 += a.z * b.z; s3 += a.w * b.w;
        }
        float s = c1b[o] + tk[l * 260 + 256] * c1ws[o * 260 + 256] + (s0 + s1) + (s2 + s3);
        c1s[o * 16 + l] = fmaxf(s, 0.0f);
    }
    __syncthreads();
    if (tid < 128) {
        int o = tid >> 3, j = tid & 7;
        p1s[tid] = fmaxf(c1s[o * 16 + 2 * j], c1s[o * 16 + 2 * j + 1]);
    }
    __syncthreads();
    if (tid < 128) {
        int oc = tid >> 2, t = tid & 3;
        float s = c2b[oc];
        for (int ic = 0; ic < 16; ic++) {
            const float* pr = &p1s[ic * 8 + t];
            const float* wr = &c2w[oc * 80 + ic * 5];
#pragma unroll
            for (int k = 0; k < 5; k++) s += pr[k] * wr[k];
        }
        flats[tid] = fmaxf(s, 0.0f);
    }
    __syncthreads();
    if (tid < 32) {
        float s = d1b[tid];
        const float4* wr = (const float4*)(d1w + tid * 128);
        const float4* fr = (const float4*)flats;
#pragma unroll 4
        for (int i = 0; i < 32; i++) {
            float4 a = fr[i], b = wr[i];
            s += a.x * b.x + a.y * b.y + a.z * b.z + a.w * b.w;
        }
        float l = fmaxf(s, 0.0f);
        lasts[tid] = l;
        out[2 * NB * TCLS + g * 32 + tid] = l;
    }
    __syncthreads();
    if (tid < TCLS) {
        float s = d2b[tid];
        const float* wr = &d2w[tid * 32];
#pragma unroll
        for (int j = 0; j < 32; j++) s += lasts[j] * wr[j];
        outs[tid] = s;
        out[NB * TCLS + g * TCLS + tid] = s;
    }
    __syncthreads();
    if (tid == 0) {
        float m = outs[0];
        for (int t = 1; t < TCLS; t++) m = fmaxf(m, outs[t]);
        float s = 0.0f;
        for (int t = 0; t < TCLS; t++) s += expf(outs[t] - m);
        lse_s = m + logf(s);
    }
    __syncthreads();
    if (tid < TCLS) out[g * TCLS + tid] = outs[tid] - lse_s;
}

extern "C" void kernel_launch(void* const* d_in, const int* in_sizes, int n_in,
                              void* d_out, int out_size)
{
    const float* x  = (const float*)d_in[0];
    const int*   ei = (const int*)  d_in[1];
    const int wb = (n_in >= 22) ? 4 : 3;
    const float* W[5]; const float* Bv[5];
    for (int i = 0; i < 5; i++) {
        W[i]  = (const float*)d_in[wb + 2 * i];
        Bv[i] = (const float*)d_in[wb + 2 * i + 1];
    }
    const float* c1w = (const float*)d_in[wb + 10];
    const float* c1b = (const float*)d_in[wb + 11];
    const float* c2w = (const float*)d_in[wb + 12];
    const float* c2b = (const float*)d_in[wb + 13];
    const float* d1w = (const float*)d_in[wb + 14];
    const float* d1b = (const float*)d_in[wb + 15];
    const float* d2w = (const float*)d_in[wb + 16];
    const float* d2b = (const float*)d_in[wb + 17];

    cudaFuncSetAttribute(dgcnn_kernel, cudaFuncAttributeMaxDynamicSharedMemorySize, SMEM_BYTES);
    dgcnn_kernel<<<NB, NT, SMEM_BYTES>>>(x, ei,
        W[0], Bv[0], W[1], Bv[1], W[2], Bv[2], W[3], Bv[3], W[4], Bv[4],
        c1w, c1b, c2w, c2b, d1w, d1b, d2w, d2b, (float*)d_out);
}

// round 17
// speedup vs baseline: 1.0390x; 1.0390x over previous
#include <cuda_runtime.h>
#include <math.h>

#define NB   512
#define NPG  256
#define EPG  4096
#define FIN  128
#define TCLS 18
#define KTOP 16
#define FSTR 256      // g_feat row: layers 0..3
#define VSH  260      // ht row stride: mult of 4 -> every row 16B-aligned
#define VSL  68       // lt row stride: mult of 4 -> every row 16B-aligned
#define NT   1024
#define RB   (VSL * 4)   // lt row stride in BYTES (272)

__device__ float g_feat[(size_t)NB * NPG * FSTR];

typedef unsigned long long ull;

static __device__ __forceinline__ ull pk2(float lo, float hi) {
    ull r; asm("mov.b64 %0, {%1, %2};" : "=l"(r) : "f"(lo), "f"(hi)); return r;
}
static __device__ __forceinline__ void upk2(ull v, float &lo, float &hi) {
    asm("mov.b64 {%0, %1}, %2;" : "=f"(lo), "=f"(hi) : "l"(v));
}
static __device__ __forceinline__ void fma2(ull &acc, ull a, ull b) {
    asm("fma.rn.f32x2 %0, %1, %2, %0;" : "+l"(acc) : "l"(a), "l"(b));
}
static __device__ __forceinline__ ull add2(ull a, ull b) {
    ull r; asm("add.rn.f32x2 %0, %1, %2;" : "=l"(r) : "l"(a), "l"(b)); return r;
}

// dynamic smem layout (words):
//   ht: 64*VSH = 16640 | lt: 257*VSL = 17476 (row 256 = zero pad) | wbufn: 2048 ull = 4096
//   invd: 256 | roff: 260 i | cnt: 256 i | eoff: 6144 u32 = 6144 words
#define W_HT   (64 * VSH)
#define W_LT   (257 * VSL)
#define W_WB   4096
#define W_WBUF_BASE (W_HT + W_LT)
#define W_EOFF_BASE (W_WBUF_BASE + W_WB + 256 + 260 + 256)
static_assert(VSH % 4 == 0,         "every ht row 16B-aligned");
static_assert(VSL % 4 == 0,         "every lt row 16B-aligned");
static_assert(W_HT % 4 == 0,        "lt base 16B");
static_assert(W_WBUF_BASE % 4 == 0, "wbufn base 16B (ulonglong2 loads)");
static_assert(W_EOFF_BASE % 4 == 0, "eoff base 16B (uint4 loads)");
#define SMEM_WORDS (W_EOFF_BASE + 6144)
#define SMEM_BYTES (SMEM_WORDS * 4)

__global__ void __launch_bounds__(NT, 1) dgcnn_kernel(
    const float* __restrict__ x, const int* __restrict__ ei,
    const float* __restrict__ w0, const float* __restrict__ b0,
    const float* __restrict__ w1, const float* __restrict__ b1,
    const float* __restrict__ w2, const float* __restrict__ b2,
    const float* __restrict__ w3, const float* __restrict__ b3,
    const float* __restrict__ w4, const float* __restrict__ b4,
    const float* __restrict__ c1w, const float* __restrict__ c1b,
    const float* __restrict__ c2w, const float* __restrict__ c2b,
    const float* __restrict__ d1w, const float* __restrict__ d1b,
    const float* __restrict__ d2w, const float* __restrict__ d2b,
    float* __restrict__ out)
{
    extern __shared__ float sm[];
    float* ht    = sm;                          // [64][VSH] channel-major features
    float* lt    = sm + W_HT;                   // [257][VSL] node-major lin
    ull*   wbufn = (ull*)(sm + W_WBUF_BASE);    // [64][32] natural channel-pair weights
    float* invd  = sm + W_WBUF_BASE + W_WB;
    int*   roff  = (int*)(invd + 256);
    int*   cnt   = roff + 260;
    unsigned int* eoff = (unsigned int*)(sm + W_EOFF_BASE);   // BYTE offsets, premult by RB
    unsigned char* s8  = (unsigned char*)wbufn;   // union (CSR build phase only)
    unsigned char* d8  = s8 + EPG;

    __shared__ float sc[NPG];
    __shared__ float w4s[64];
    __shared__ int   ord[KTOP];
    __shared__ float c1s[256];
    __shared__ float p1s[128];
    __shared__ float flats[128];
    __shared__ float lasts[32];
    __shared__ float outs[TCLS];
    __shared__ float lse_s;

    const int g = blockIdx.x, tid = threadIdx.x;
    const int eb = g * EPG;

    // ---- edges: graph base 256-aligned, low 8 bits = local id ----
    for (int e = tid; e < EPG; e += NT) {
        s8[e] = (unsigned char)(ei[eb + e] & 255);
        d8[e] = (unsigned char)(ei[(size_t)NB * EPG + eb + e] & 255);
    }
    int* dcn = (int*)ht;  // scratch
    if (tid < NPG) { cnt[tid] = 1; dcn[tid] = 1; }   // dcn starts at 1: self edge in list
    if (tid < VSL) lt[256 * VSL + tid] = 0.0f;       // zero pad row (dummy gather target)
    __syncthreads();
    for (int e = tid; e < EPG; e += NT) {
        atomicAdd(&cnt[s8[e]], 1);
        atomicAdd(&dcn[d8[e]], 1);
    }
    __syncthreads();
    if (tid < NPG) {
        invd[tid] = 1.0f / (float)cnt[tid];
        dcn[tid] = (dcn[tid] + 7) & ~7;          // pad to multiple of 8
    }
    __syncthreads();
    for (int s = 1; s < NPG; s <<= 1) {          // inclusive scan
        int t = 0;
        if (tid < NPG) { t = dcn[tid]; if (tid >= s) t += dcn[tid - s]; }
        __syncthreads();
        if (tid < NPG) dcn[tid] = t;
        __syncthreads();
    }
    if (tid < NPG) roff[tid + 1] = dcn[tid];
    if (tid == 0)  roff[0] = 0;
    __syncthreads();
    if (tid < NPG) {   // self edge occupies first slot; cursor starts after it
        eoff[roff[tid]] = (unsigned int)(tid * RB);
        cnt[tid] = roff[tid] + 1;
    }
    __syncthreads();
    for (int e = tid; e < EPG; e += NT) {
        int p = atomicAdd(&cnt[d8[e]], 1);
        eoff[p] = (unsigned int)((int)s8[e] * RB);   // premultiplied BYTE offset
    }
    __syncthreads();
    if (tid < NPG) {
        int p = cnt[tid], p1 = roff[tid + 1];
        for (; p < p1; p++) eoff[p] = (unsigned int)(256 * RB);  // dummy -> zero row
    }
    __syncthreads();

    const float* Wp[4] = {w0, w1, w2, w3};
    const float* Bp[4] = {b0, b1, b2, b3};
    const int lane  = tid & 31;
    const int cgp   = (tid >> 5) & 7;    // channel group (8 ch)
    const int ngp   = tid >> 8;          // node slice (0..3)
    const int c8    = cgp * 8;
    const int pbase = 2 * (lane + 32 * ngp);   // node pair (pbase, pbase+1)

    // ---- layers 0..3 ----
    for (int L = 0; L < 4; L++) {
        ull accA[4], accB[4];   // accA: node pbase, ch (c8+2j, c8+2j+1); accB: node pbase+1
#pragma unroll
        for (int t = 0; t < 4; t++) { accA[t] = 0ull; accB[t] = 0ull; }
        const int nch = (L == 0) ? 2 : 1;
        for (int ch = 0; ch < nch; ch++) {
            if (L == 0) {
                for (int i = tid; i < NPG * 16; i += NT) {
                    int n = i >> 4, kq = i & 15;
                    float4 v = *(const float4*)(x + (size_t)(g * NPG + n) * FIN + ch * 64 + kq * 4);
                    ht[(kq * 4 + 0) * VSH + n] = v.x;
                    ht[(kq * 4 + 1) * VSH + n] = v.y;
                    ht[(kq * 4 + 2) * VSH + n] = v.z;
                    ht[(kq * 4 + 3) * VSH + n] = v.w;
                }
            }
            // stage weights as NATURAL channel pairs: wbufn[k*32 + j2] = (w[2j2][k], w[2j2+1][k])
            {
                const float* WL = Wp[L];
                for (int i = tid; i < 2048; i += NT) {
                    int j2 = i & 31, k = i >> 5;
                    float wlo, whi;
                    if (L == 0) {
                        wlo = WL[(2 * j2)     * FIN + ch * 64 + k];
                        whi = WL[(2 * j2 + 1) * FIN + ch * 64 + k];
                    } else {
                        wlo = WL[(2 * j2)     * 64 + k];
                        whi = WL[(2 * j2 + 1) * 64 + k];
                    }
                    wbufn[k * 32 + j2] = pk2(wlo, whi);
                }
            }
            __syncthreads();
            // GEMM: per k: 1 LDS.64 (node pair) + 2 LDS.128 (natural-pair weights) + 8 FFMA2
#pragma unroll 2
            for (int k = 0; k < 64; k++) {
                ull hp = *(const ull*)(ht + k * VSH + pbase);
                float h0, h1; upk2(hp, h0, h1);
                ull d0 = pk2(h0, h0), d1 = pk2(h1, h1);
                const ulonglong2* wp = (const ulonglong2*)(wbufn + k * 32 + 4 * cgp);
                ulonglong2 wa = wp[0], wb = wp[1];
                fma2(accA[0], d0, wa.x); fma2(accA[1], d0, wa.y);
                fma2(accA[2], d0, wb.x); fma2(accA[3], d0, wb.y);
                fma2(accB[0], d1, wa.x); fma2(accB[1], d1, wa.y);
                fma2(accB[2], d1, wb.x); fma2(accB[3], d1, wb.y);
            }
            // barrier only needed before re-staging ht/wbufn for the next chunk;
            // the final chunk's GEMM is protected by the post-bias barrier (bias
            // writes only lt, which GEMM never touches).
            if (ch + 1 < nch) __syncthreads();
        }
        // bias (f32x2) + store lin node-major: 2 STS.128 per node row
        {
            const float* bb = Bp[L];
#pragma unroll
            for (int t = 0; t < 4; t++) {
                ull bp = pk2(bb[c8 + 2 * t], bb[c8 + 2 * t + 1]);
                accA[t] = add2(accA[t], bp);
                accB[t] = add2(accB[t], bp);
            }
            ulonglong2* r0 = (ulonglong2*)(lt + pbase * VSL + c8);
            ulonglong2* r1 = (ulonglong2*)(lt + (pbase + 1) * VSL + c8);
            r0[0] = make_ulonglong2(accA[0], accA[1]);
            r0[1] = make_ulonglong2(accA[2], accA[3]);
            r1[0] = make_ulonglong2(accB[0], accB[1]);
            r1[1] = make_ulonglong2(accB[2], accB[3]);
        }
        __syncthreads();
        // aggregation: lane = channel pair (c2,c2+1); byte-offset edges; self edge in list
        {
            const int c2 = 2 * lane;
            const int grp = tid >> 5;            // 0..31
            const char* lcb = (const char*)(lt + c2);
#pragma unroll
            for (int r = 0; r < 2; r++) {
                const int vb = 4 * grp + 128 * r;
                float tlo[4], thi[4];
#pragma unroll
                for (int j = 0; j < 4; j++) {
                    const int v = vb + j;
                    ull a0 = 0, a1 = 0, a2 = 0, a3 = 0;
                    int e = roff[v], e1 = roff[v + 1];
                    for (; e < e1; e += 8) {
                        uint4 p0 = *(const uint4*)(eoff + e);
                        uint4 p1 = *(const uint4*)(eoff + e + 4);
                        a0 = add2(a0, *(const ull*)(lcb + p0.x));
                        a1 = add2(a1, *(const ull*)(lcb + p0.y));
                        a2 = add2(a2, *(const ull*)(lcb + p0.z));
                        a3 = add2(a3, *(const ull*)(lcb + p0.w));
                        a0 = add2(a0, *(const ull*)(lcb + p1.x));
                        a1 = add2(a1, *(const ull*)(lcb + p1.y));
                        a2 = add2(a2, *(const ull*)(lcb + p1.z));
                        a3 = add2(a3, *(const ull*)(lcb + p1.w));
                    }
                    ull s = add2(add2(a0, a1), add2(a2, a3));
                    float x0, x1; upk2(s, x0, x1);
                    float iv = invd[v];
                    float t0 = tanhf(x0 * iv);
                    float t1 = tanhf(x1 * iv);
                    tlo[j] = t0; thi[j] = t1;
                    *(float2*)(g_feat + (size_t)(g * NPG + v) * FSTR + L * 64 + c2) = make_float2(t0, t1);
                }
                *(float4*)(ht + c2 * VSH + vb)       = make_float4(tlo[0], tlo[1], tlo[2], tlo[3]);
                *(float4*)(ht + (c2 + 1) * VSH + vb) = make_float4(thi[0], thi[1], thi[2], thi[3]);
            }
        }
        __syncthreads();
    }

    // ---- layer 4: sort scores ----
    if (tid < 64) w4s[tid] = w4[tid];
    __syncthreads();
    if (tid < NPG) {
        float s = b4[0];
#pragma unroll 4
        for (int k = 0; k < 64; k++) s += ht[k * VSH + tid] * w4s[k];
        lt[tid * VSL] = s;
    }
    __syncthreads();
    if (tid < NPG) {
        const char* ltb = (const char*)lt;
        float a0 = 0.f, a1 = 0.f, a2 = 0.f, a3 = 0.f;   // self edge is in the list
        int e = roff[tid], e1 = roff[tid + 1];
        for (; e < e1; e += 8) {
            uint4 p0 = *(const uint4*)(eoff + e);
            uint4 p1 = *(const uint4*)(eoff + e + 4);
            a0 += *(const float*)(ltb + p0.x); a1 += *(const float*)(ltb + p0.y);
            a2 += *(const float*)(ltb + p0.z); a3 += *(const float*)(ltb + p0.w);
            a0 += *(const float*)(ltb + p1.x); a1 += *(const float*)(ltb + p1.y);
            a2 += *(const float*)(ltb + p1.z); a3 += *(const float*)(ltb + p1.w);
        }
        float a = (a0 + a1) + (a2 + a3);
        sc[tid] = tanhf(a * invd[tid]);
    }
    __syncthreads();

    // ---- stable top-16: single warp shfl (val desc, idx asc) ----
    if (tid < 32) {
        float v[8];
        const int base = tid * 8;
#pragma unroll
        for (int t = 0; t < 8; t++) v[t] = sc[base + t];
        for (int r = 0; r < KTOP; r++) {
            float bv = v[0]; int bi = base;
#pragma unroll
            for (int t = 1; t < 8; t++)
                if (v[t] > bv) { bv = v[t]; bi = base + t; }
#pragma unroll
            for (int off = 16; off > 0; off >>= 1) {
                float ov = __shfl_xor_sync(0xffffffffu, bv, off);
                int   oi = __shfl_xor_sync(0xffffffffu, bi, off);
                if (ov > bv || (ov == bv && oi < bi)) { bv = ov; bi = oi; }
            }
            if (tid == 0) ord[r] = bi;
            if ((bi >> 3) == tid) v[bi & 7] = -3.4e38f;
        }
    }
    __syncthreads();

    // ---- head (tk in lt, c1ws in ht; both stride 260) ----
    float* tk   = lt;
    float* c1ws = ht;
    for (int i = tid; i < 16 * 257; i += NT) {
        int o = i / 257, d = i - o * 257;
        c1ws[o * 260 + d] = c1w[i];
    }
    for (int i = tid; i < KTOP * 257; i += NT) {
        int l = i / 257, d = i - l * 257;
        tk[l * 260 + d] = (d < 256) ? g_feat[(size_t)(g * NPG + ord[l]) * FSTR + d] : sc[ord[l]];
    }
    __syncthreads();

    if (tid < 256) {
        int o = tid & 15, l = tid >> 4;
        const float4* tr = (const float4*)(tk + l * 260);
        const float4* wr = (const float4*)(c1ws + o * 260);
        float s0 = 0.f, s1 = 0.f, s2 = 0.f, s3 = 0.f;
#pragma unroll 4
        for (int d = 0; d < 64; d++) {
            float4 a = tr[d], b = wr[d];
            s0 += a.x * b.x; s1 += a.y * b.y; s2 += a.z * b.z; s3 += a.w * b.w;
        }
        float s = c1b[o] + tk[l * 260 + 256] * c1ws[o * 260 + 256] + (s0 + s1) + (s2 + s3);
        c1s[o * 16 + l] = fmaxf(s, 0.0f);
    }
    __syncthreads();
    if (tid < 128) {
        int o = tid >> 3, j = tid & 7;
        p1s[tid] = fmaxf(c1s[o * 16 + 2 * j], c1s[o * 16 + 2 * j + 1]);
    }
    __syncthreads();
    if (tid < 128) {
        int oc = tid >> 2, t = tid & 3;
        float s = c2b[oc];
        for (int ic = 0; ic < 16; ic++) {
            const float* pr = &p1s[ic * 8 + t];
            const float* wr = &c2w[oc * 80 + ic * 5];
#pragma unroll
            for (int k = 0; k < 5; k++) s += pr[k] * wr[k];
        }
        flats[tid] = fmaxf(s, 0.0f);
    }
    __syncthreads();
    if (tid < 32) {
        float s = d1b[tid];
        const float4* wr = (const float4*)(d1w + tid * 128);
        const float4* fr = (const float4*)flats;
#pragma unroll 4
        for (int i = 0; i < 32; i++) {
            float4 a = fr[i], b = wr[i];
            s += a.x * b.x + a.y * b.y + a.z * b.z + a.w * b.w;
        }
        float l = fmaxf(s, 0.0f);
        lasts[tid] = l;
        out[2 * NB * TCLS + g * 32 + tid] = l;
    }
    __syncthreads();
    if (tid < TCLS) {
        float s = d2b[tid];
        const float* wr = &d2w[tid * 32];
#pragma unroll
        for (int j = 0; j < 32; j++) s += lasts[j] * wr[j];
        outs[tid] = s;
        out[NB * TCLS + g * TCLS + tid] = s;
    }
    __syncthreads();
    if (tid == 0) {
        float m = outs[0];
        for (int t = 1; t < TCLS; t++) m = fmaxf(m, outs[t]);
        float s = 0.0f;
        for (int t = 0; t < TCLS; t++) s += expf(outs[t] - m);
        lse_s = m + logf(s);
    }
    __syncthreads();
    if (tid < TCLS) out[g * TCLS + tid] = outs[tid] - lse_s;
}

extern "C" void kernel_launch(void* const* d_in, const int* in_sizes, int n_in,
                              void* d_out, int out_size)
{
    const float* x  = (const float*)d_in[0];
    const int*   ei = (const int*)  d_in[1];
    const int wb = (n_in >= 22) ? 4 : 3;
    const float* W[5]; const float* Bv[5];
    for (int i = 0; i < 5; i++) {
        W[i]  = (const float*)d_in[wb + 2 * i];
        Bv[i] = (const float*)d_in[wb + 2 * i + 1];
    }
    const float* c1w = (const float*)d_in[wb + 10];
    const float* c1b = (const float*)d_in[wb + 11];
    const float* c2w = (const float*)d_in[wb + 12];
    const float* c2b = (const float*)d_in[wb + 13];
    const float* d1w = (const float*)d_in[wb + 14];
    const float* d1b = (const float*)d_in[wb + 15];
    const float* d2w = (const float*)d_in[wb + 16];
    const float* d2b = (const float*)d_in[wb + 17];

    cudaFuncSetAttribute(dgcnn_kernel, cudaFuncAttributeMaxDynamicSharedMemorySize, SMEM_BYTES);
    dgcnn_kernel<<<NB, NT, SMEM_BYTES>>>(x, ei,
        W[0], Bv[0], W[1], Bv[1], W[2], Bv[2], W[3], Bv[3], W[4], Bv[4],
        c1w, c1b, c2w, c2b, d1w, d1b, d2w, d2b, (float*)d_out);
}